// round 12
// baseline (speedup 1.0000x reference)
#include <cuda_runtime.h>
#include <cuda_bf16.h>

// Embedding gather: out[n, :] = embeddings[inputs[n], :]
// N = 16384 rows, EMB = 128 floats = 32 float4 per row.
//
// FINAL (committed, session best: 5.824 us ncu / 6.624 us harness):
// warp-cooperative, 4 rows per warp.
//   - lane 0 fetches all 4 row indices in ONE LDG.128 (int4)
//   - __shfl_sync broadcasts each index from lane 0 (off the memory chain)
//   - 4 independent LDG.128 gathers per thread (per-warp MLP=4), then
//     4 coalesced 512B row stores
// Chain: 1 idx load -> shfl -> 4 parallel gathers.
// Grid: 512 blocks x 256 threads = 4096 warps x 4 rows = 16384 rows.
//
// Session conclusion (11 rounds, 9 configs, 8x occupancy / 8x MLP sweeps,
// serial vs shfl chains): all configs land 5.82-6.66 us with +/-0.2 us
// run-to-run noise on identical binaries; every pipe <16% in every run.
// Duration = ~5 us fixed launch/dispatch/drain floor + ~1 us irreducible
// latency-bound gather. All perturbations off this point measured and
// regressed; this is the converged optimum.

#define N_ROWS   16384
#define EMB_F4   32                  // float4 per row
#define THREADS  256
#define ROWS_PER_WARP 4
#define WARPS_TOTAL   (N_ROWS / ROWS_PER_WARP)        // 4096
#define NBLOCKS       (WARPS_TOTAL / (THREADS / 32))  // 512

__global__ __launch_bounds__(THREADS)
void onehot_embed_gather_final(const int* __restrict__ idx,
                               const float4* __restrict__ emb,   // [VOCAB, 32]
                               float4* __restrict__ out)          // [N, 32]
{
    const int warp = (blockIdx.x * THREADS + threadIdx.x) >> 5;
    const int lane = threadIdx.x & 31;
    const int row0 = warp * ROWS_PER_WARP;

    // Lane 0: one LDG.128 carrying all 4 row indices for this warp.
    int4 packed = make_int4(0, 0, 0, 0);
    if (lane == 0)
        packed = __ldg((const int4*)(idx + row0));

    // Broadcast the 4 indices from lane 0; all gathers depend on one memory op.
    int e[ROWS_PER_WARP];
    e[0] = __shfl_sync(0xFFFFFFFFu, packed.x, 0);
    e[1] = __shfl_sync(0xFFFFFFFFu, packed.y, 0);
    e[2] = __shfl_sync(0xFFFFFFFFu, packed.z, 0);
    e[3] = __shfl_sync(0xFFFFFFFFu, packed.w, 0);

    // 4 independent 16B gather loads in flight (per-warp MLP = 4).
    float4 v[ROWS_PER_WARP];
    #pragma unroll
    for (int r = 0; r < ROWS_PER_WARP; r++)
        v[r] = __ldg(&emb[(long long)e[r] * EMB_F4 + lane]);

    // Coalesced stores (each row = one full warp-wide 512B store).
    #pragma unroll
    for (int r = 0; r < ROWS_PER_WARP; r++)
        out[(row0 + r) * EMB_F4 + lane] = v[r];
}

extern "C" void kernel_launch(void* const* d_in, const int* in_sizes, int n_in,
                              void* d_out, int out_size)
{
    const int*    idx = (const int*)   d_in[0];   // int32 [16384]
    const float4* emb = (const float4*)d_in[1];   // float32 [32000,128]
    float4*       out = (float4*)      d_out;     // float32 [16384,128]

    onehot_embed_gather_final<<<NBLOCKS, THREADS>>>(idx, emb, out);
}